// round 7
// baseline (speedup 1.0000x reference)
#include <cuda_runtime.h>

// CommNet forward: B=8192, N=64, D=128, O=16
//   H1 = tanh(wH1*obs); C1 = (sum_n H1 - H1)/(N-1)
//   H2 = tanh(wH2*H1 + wC2*C1) + obs ; out = H2 @ w_out + b_out
//
// One CTA per batch element, 128 threads.
// - w_out/b_out in __constant__ (loop-uniform LDCU -> zero L1 traffic)
// - h tile: u64 agent-pairs, XOR-swizzled (conflict-free col-write/row-read)
// - GEMV: warp = d-quarter, lane = agent-pair, f32x2 FMA with o-pair packing
// - cross-warp d-reduction via smem partials overlaid on the tile

#define N_AG 64
#define DIM  128
#define OUTD 16

typedef unsigned long long u64;

__constant__ u64 c_w2[DIM * OUTD / 2];   // (w[d][2j], w[d][2j+1]) pairs, 8 KB
__constant__ u64 c_b2[OUTD / 2];         // (b[2j], b[2j+1]) pairs

__device__ __forceinline__ float tanh_fast(float x) {
    float y; asm("tanh.approx.f32 %0, %1;" : "=f"(y) : "f"(x)); return y;
}
__device__ __forceinline__ u64 pack2(float lo, float hi) {
    u64 r; asm("mov.b64 %0, {%1, %2};" : "=l"(r) : "f"(lo), "f"(hi)); return r;
}
__device__ __forceinline__ void unpack2(u64 v, float& lo, float& hi) {
    asm("mov.b64 {%0, %1}, %2;" : "=f"(lo), "=f"(hi) : "l"(v));
}
__device__ __forceinline__ void ffma2(u64& d, u64 a, u64 b) {
    asm("fma.rn.f32x2 %0, %1, %2, %0;" : "+l"(d) : "l"(a), "l"(b));
}
__device__ __forceinline__ u64 fadd2(u64 a, u64 b) {
    u64 r; asm("add.rn.f32x2 %0, %1, %2;" : "=l"(r) : "l"(a), "l"(b)); return r;
}
__device__ __forceinline__ u64 fmul2(u64 a, u64 b) {
    u64 r; asm("mul.rn.f32x2 %0, %1, %2;" : "=l"(r) : "l"(a), "l"(b)); return r;
}
__device__ __forceinline__ u64 ffma2r(u64 a, u64 b, u64 c) {
    u64 r; asm("fma.rn.f32x2 %0, %1, %2, %3;" : "=l"(r) : "l"(a), "l"(b), "l"(c)); return r;
}

// XOR-swizzled tile address (u64 units): row d, agent-pair n2
__device__ __forceinline__ int tadr(int d, int n2) {
    return d * 32 + (n2 ^ (d & 31));
}

__global__ __launch_bounds__(128)
void commnet_kernel(const float* __restrict__ obs,
                    const float* __restrict__ wH1,
                    const float* __restrict__ wH2,
                    const float* __restrict__ wC2,
                    float* __restrict__ out)
{
    __shared__ __align__(16) u64 buf[DIM * 32];   // 32 KB: h-tile, then partials

    const int tid = threadIdx.x;                  // = feature d in phase part
    const int b   = blockIdx.x;

    // ---- load obs column d=tid as 32 agent-pairs (64 coalesced LDG.32) ----
    const float* ob = obs + (size_t)b * (N_AG * DIM) + tid;
    u64 xp[32];
    #pragma unroll 8
    for (int k = 0; k < 32; k++) {
        float xa = ob[(2 * k) * DIM];
        float xb = ob[(2 * k + 1) * DIM];
        xp[k] = pack2(xa, xb);
    }

    const float a1 = wH1[tid];
    const float a2 = wH2[tid];
    const float c2 = wC2[tid];
    const u64 a1p = pack2(a1, a1);

    // ---- pass 1: h1 = tanh(a1*x); accumulate sum; store h1 pairs to tile ----
    u64 sum2 = 0ull;                               // (0.f, 0.f)
    #pragma unroll 8
    for (int k = 0; k < 32; k++) {
        u64 t = fmul2(a1p, xp[k]);
        float tl, th; unpack2(t, tl, th);
        u64 h1p = pack2(tanh_fast(tl), tanh_fast(th));
        sum2 = fadd2(sum2, h1p);
        buf[tadr(tid, k)] = h1p;
    }
    float sl, sh; unpack2(sum2, sl, sh);
    const float sum = sl + sh;
    const float inv = 1.0f / (float)(N_AG - 1);

    // ---- pass 2: h2 = tanh(a2*h1 + c2*(sum-h1)*inv) + x ; overwrite tile ----
    const u64 a2p  = pack2(a2, a2);
    const u64 c2p  = pack2(c2, c2);
    const u64 ninv = pack2(-inv, -inv);
    const u64 sip  = pack2(sum * inv, sum * inv);
    #pragma unroll 8
    for (int k = 0; k < 32; k++) {
        u64 h1p = buf[tadr(tid, k)];
        u64 c1p = ffma2r(h1p, ninv, sip);          // (sum - h1) * inv
        u64 arg = ffma2r(c2p, c1p, fmul2(a2p, h1p));
        float al, ah; unpack2(arg, al, ah);
        u64 h2p = fadd2(pack2(tanh_fast(al), tanh_fast(ah)), xp[k]);
        buf[tadr(tid, k)] = h2p;
    }
    __syncthreads();

    // ---- GEMV: warp w = d-quarter, lane p = agent-pair; all 16 outputs ----
    const int w = tid >> 5;
    const int p = tid & 31;

    u64 acc0[8], acc1[8];                          // agent 2p / 2p+1, o-pairs
    #pragma unroll
    for (int j = 0; j < 8; j++) {
        acc0[j] = (w == 0) ? c_b2[j] : 0ull;       // bias folded into warp 0
        acc1[j] = (w == 0) ? c_b2[j] : 0ull;
    }

    const int dbase = w * 32;
    #pragma unroll
    for (int i = 0; i < 32; i++) {
        const int d = dbase + i;
        u64 hv = buf[d * 32 + (p ^ i)];            // LDS.64, conflict-free
        float hlo, hhi; unpack2(hv, hlo, hhi);
        u64 hA = pack2(hlo, hlo);
        u64 hB = pack2(hhi, hhi);
        #pragma unroll
        for (int j = 0; j < 8; j++) {
            u64 wv = c_w2[d * 8 + j];              // uniform constant load
            ffma2(acc0[j], hA, wv);
            ffma2(acc1[j], hB, wv);
        }
    }
    __syncthreads();                               // all tile reads done

    // ---- write d-partial sums (overlay tile); pitch 17 avoids conflicts ----
    u64* part = buf;
    #pragma unroll
    for (int j = 0; j < 8; j++) {
        part[w * 544 + p * 17 + j]     = acc0[j];  // agent 2p
        part[w * 544 + p * 17 + 8 + j] = acc1[j];  // agent 2p+1
    }
    __syncthreads();

    // ---- final combine + store: thread t -> agent n=t>>1, o-pairs j0..j0+3 ----
    {
        const int n  = tid >> 1;
        const int j0 = (tid & 1) * 4;
        const int pp = n >> 1;
        const int e0 = (n & 1) * 8 + j0;
        u64 r[4];
        #pragma unroll
        for (int k = 0; k < 4; k++) {
            u64 s = part[0 * 544 + pp * 17 + e0 + k];
            s = fadd2(s, part[1 * 544 + pp * 17 + e0 + k]);
            s = fadd2(s, part[2 * 544 + pp * 17 + e0 + k]);
            s = fadd2(s, part[3 * 544 + pp * 17 + e0 + k]);
            r[k] = s;
        }
        // out u64 index = n*8 + j0 + k = tid*4 + k  -> 2 coalesced STG.128
        ulonglong2* o2 = (ulonglong2*)(out + (size_t)b * (N_AG * OUTD));
        o2[tid * 2 + 0] = make_ulonglong2(r[0], r[1]);
        o2[tid * 2 + 1] = make_ulonglong2(r[2], r[3]);
    }
}

extern "C" void kernel_launch(void* const* d_in, const int* in_sizes, int n_in,
                              void* d_out, int out_size) {
    const float* obs  = (const float*)d_in[0];
    const float* wH1  = (const float*)d_in[1];
    // d_in[2] = w_C1: multiplies C0 = 0 -> unused
    const float* wH2  = (const float*)d_in[3];
    const float* wC2  = (const float*)d_in[4];
    const float* wout = (const float*)d_in[5];
    const float* bout = (const float*)d_in[6];
    float* out = (float*)d_out;

    // Stage w_out / b_out into constant memory (D2D async, graph-capturable)
    cudaMemcpyToSymbolAsync(c_w2, wout, DIM * OUTD * sizeof(float), 0,
                            cudaMemcpyDeviceToDevice);
    cudaMemcpyToSymbolAsync(c_b2, bout, OUTD * sizeof(float), 0,
                            cudaMemcpyDeviceToDevice);

    int B = in_sizes[0] / (N_AG * DIM);   // 8192
    commnet_kernel<<<B, 128>>>(obs, wH1, wH2, wC2, out);
}

// round 8
// speedup vs baseline: 1.7111x; 1.7111x over previous
#include <cuda_runtime.h>

// CommNet forward: B=8192, N=64, D=128, O=16
//   H1 = tanh(wH1*obs); C1 = (sum_n H1 - H1)/(N-1)
//   H2 = tanh(wH2*H1 + wC2*C1) + obs ; out = H2 @ w_out + b_out
//
// One CTA per batch element, 128 threads.
// Phase: thread = feature d, obs column in registers (as R6, proven).
// Tile: u64 agent-pairs, layout [d][chunk] pitch 32 u64, chunk-XOR swizzle.
// GEMV: warp = d-quarter, lane = (agent-octet a8, o-quad j). h arrives as
//   natural u64 pairs -> FFMA2; w is one broadcast float4 per d.
// 4-way d-reduction via smem partials (overlaid on tile), then combiner.

#define N_AG 64
#define DIM  128
#define OUTD 16

typedef unsigned long long u64;

__device__ __forceinline__ float tanh_fast(float x) {
    float y; asm("tanh.approx.f32 %0, %1;" : "=f"(y) : "f"(x)); return y;
}
__device__ __forceinline__ u64 pack2(float lo, float hi) {
    u64 r; asm("mov.b64 %0, {%1, %2};" : "=l"(r) : "f"(lo), "f"(hi)); return r;
}
__device__ __forceinline__ void unpack2(u64 v, float& lo, float& hi) {
    asm("mov.b64 {%0, %1}, %2;" : "=f"(lo), "=f"(hi) : "l"(v));
}
__device__ __forceinline__ void ffma2(u64& d, u64 a, u64 b) {
    asm("fma.rn.f32x2 %0, %1, %2, %0;" : "+l"(d) : "l"(a), "l"(b));
}

__global__ __launch_bounds__(128)
void commnet_kernel(const float* __restrict__ obs,
                    const float* __restrict__ wH1,
                    const float* __restrict__ wH2,
                    const float* __restrict__ wC2,
                    const float* __restrict__ wout,
                    const float* __restrict__ bout,
                    float* __restrict__ out)
{
    // hs: h2 tile [d=128][32 u64 agent-pairs], chunk-swizzled. 32 KB.
    // After GEMV it is reused as partials: part[4 warps][32 lanes][18] u64.
    __shared__ __align__(16) u64   hs[DIM * 32];
    __shared__ __align__(16) float wsm[DIM * OUTD];   // 8 KB
    __shared__ float bsm[OUTD];

    const int tid = threadIdx.x;                      // = feature d for phase
    const int b   = blockIdx.x;

    // ---- stage w_out / b_out ----
    {
        const float4* w4  = (const float4*)wout;
        float4*       ws4 = (float4*)wsm;
        #pragma unroll
        for (int i = 0; i < 4; i++)
            ws4[i * 128 + tid] = w4[i * 128 + tid];
        if (tid < OUTD) bsm[tid] = bout[tid];
    }

    // ---- obs column d=tid into registers: 64 coalesced LDG.32 ----
    const float* ob = obs + (size_t)b * (N_AG * DIM) + tid;
    float x[N_AG];
    #pragma unroll
    for (int n = 0; n < N_AG; n++)
        x[n] = ob[n * DIM];

    const float a1 = wH1[tid];
    const float a2 = wH2[tid];
    const float c2 = wC2[tid];

    // ---- pass 1: sum of tanh over agents (registers only) ----
    float sum = 0.0f;
    #pragma unroll
    for (int n = 0; n < N_AG; n++)
        sum += tanh_fast(a1 * x[n]);
    const float inv = 1.0f / (float)(N_AG - 1);

    // ---- pass 2: h2 per chunk of 4 agents -> swizzled STS.128 ----
    {
        u64* row = &hs[tid * 32];
        const int sw = tid & 15;
        #pragma unroll
        for (int m = 0; m < 16; m++) {                // chunk m: agents 4m..4m+3
            float h2v[4];
            #pragma unroll
            for (int e = 0; e < 4; e++) {
                float xv = x[4 * m + e];
                float h1 = tanh_fast(a1 * xv);
                h2v[e] = tanh_fast(a2 * h1 + c2 * (sum - h1) * inv) + xv;
            }
            ulonglong2 v = make_ulonglong2(pack2(h2v[0], h2v[1]),
                                           pack2(h2v[2], h2v[3]));
            *(ulonglong2*)&row[(m ^ sw) << 1] = v;
        }
    }
    __syncthreads();

    // ---- GEMV: warp w = d-quarter; lane = (a8 = l&7 agent-octet, j = l>>3 o-quad)
    const int w  = tid >> 5;
    const int l  = tid & 31;
    const int a8 = l & 7;
    const int j  = l >> 3;

    u64 acc[4][4];                                    // [agent-pair ap][o]
    #pragma unroll
    for (int ap = 0; ap < 4; ap++)
        #pragma unroll
        for (int o = 0; o < 4; o++) acc[ap][o] = 0ull;

    const int dbase = w * 32;
    #pragma unroll
    for (int i = 0; i < 32; i++) {
        const int d  = dbase + i;
        const int sw = d & 15;
        const u64* row = &hs[d * 32];
        ulonglong2 hv0 = *(const ulonglong2*)&row[((2 * a8)     ^ sw) << 1];
        ulonglong2 hv1 = *(const ulonglong2*)&row[((2 * a8 + 1) ^ sw) << 1];
        u64 hp0 = hv0.x, hp1 = hv0.y, hp2 = hv1.x, hp3 = hv1.y;

        float4 wq = *(const float4*)&wsm[d * OUTD + j * 4];   // broadcast
        u64 wd0 = pack2(wq.x, wq.x);
        u64 wd1 = pack2(wq.y, wq.y);
        u64 wd2 = pack2(wq.z, wq.z);
        u64 wd3 = pack2(wq.w, wq.w);

        ffma2(acc[0][0], hp0, wd0); ffma2(acc[0][1], hp0, wd1);
        ffma2(acc[0][2], hp0, wd2); ffma2(acc[0][3], hp0, wd3);
        ffma2(acc[1][0], hp1, wd0); ffma2(acc[1][1], hp1, wd1);
        ffma2(acc[1][2], hp1, wd2); ffma2(acc[1][3], hp1, wd3);
        ffma2(acc[2][0], hp2, wd0); ffma2(acc[2][1], hp2, wd1);
        ffma2(acc[2][2], hp2, wd2); ffma2(acc[2][3], hp2, wd3);
        ffma2(acc[3][0], hp3, wd0); ffma2(acc[3][1], hp3, wd1);
        ffma2(acc[3][2], hp3, wd2); ffma2(acc[3][3], hp3, wd3);
    }
    __syncthreads();                                  // all tile reads done

    // ---- write partials: part[w][l][slot = ap*4+o], pitch 18 u64 ----
    {
        u64* part = hs;
        u64* dst = &part[w * 576 + l * 18];
        #pragma unroll
        for (int ap = 0; ap < 4; ap++) {
            *(ulonglong2*)&dst[ap * 4 + 0] = make_ulonglong2(acc[ap][0], acc[ap][1]);
            *(ulonglong2*)&dst[ap * 4 + 2] = make_ulonglong2(acc[ap][2], acc[ap][3]);
        }
    }
    __syncthreads();

    // ---- combine + store: thread t -> agent n = t>>1, o-range (t&1)*8..+8 ----
    {
        const u64* part = hs;
        const int n    = tid >> 1;
        const int a8c  = n >> 3;
        const int apc  = (n >> 1) & 3;
        const int half = n & 1;

        float res[8];
        #pragma unroll
        for (int k = 0; k < 4; k++) {
            const int op = (tid & 1) * 4 + k;         // o-pair index 0..7
            const int lp = a8c + 8 * (op >> 1);       // source lane
            const int s0 = apc * 4 + 2 * (op & 1);    // slot of o=2op
            float lo = 0.0f, hi = 0.0f;
            #pragma unroll
            for (int wp = 0; wp < 4; wp++) {
                ulonglong2 v = *(const ulonglong2*)&part[wp * 576 + lp * 18 + s0];
                float e0l, e0h, e1l, e1h;
                unpack2(v.x, e0l, e0h);
                unpack2(v.y, e1l, e1h);
                lo += half ? e0h : e0l;
                hi += half ? e1h : e1l;
            }
            res[2 * k]     = lo + bsm[2 * op];
            res[2 * k + 1] = hi + bsm[2 * op + 1];
        }
        float4* of = (float4*)(out + (size_t)b * (N_AG * OUTD));
        of[2 * tid + 0] = make_float4(res[0], res[1], res[2], res[3]);
        of[2 * tid + 1] = make_float4(res[4], res[5], res[6], res[7]);
    }
}

extern "C" void kernel_launch(void* const* d_in, const int* in_sizes, int n_in,
                              void* d_out, int out_size) {
    const float* obs  = (const float*)d_in[0];
    const float* wH1  = (const float*)d_in[1];
    // d_in[2] = w_C1: multiplies C0 = 0 -> unused
    const float* wH2  = (const float*)d_in[3];
    const float* wC2  = (const float*)d_in[4];
    const float* wout = (const float*)d_in[5];
    const float* bout = (const float*)d_in[6];
    float* out = (float*)d_out;

    int B = in_sizes[0] / (N_AG * DIM);   // 8192
    commnet_kernel<<<B, 128>>>(obs, wH1, wH2, wC2, wout, bout, out);
}

// round 9
// speedup vs baseline: 1.7356x; 1.0143x over previous
#include <cuda_runtime.h>

// CommNet forward: B=8192, N=64, D=128, O=16
//   H1 = tanh(wH1*obs); C1 = (sum_n H1 - H1)/(N-1)
//   H2 = tanh(wH2*H1 + wC2*C1) + obs ; out = H2 @ w_out + b_out
//
// One CTA per batch element, 128 threads.
// Phase: thread = feature d; obs read twice (2nd pass hits L1) -> low regs,
//        5 CTAs/SM.
// Tile: row-major [d][n] floats, pitch 68 (17 16B-units: odd -> conflict-free
//       row-strided STS.128 / LDS.128).
// GEMV: warp = d-quarter; lane = (agent-octet p, o-quad q). Per d: 2 h-LDS.128
//       (agents arrive as natural u64 pairs) + 1 w-LDS.128 -> 16 FFMA2.
// 4-way d-reduction via smem partials overlaid on the tile.

#define N_AG 64
#define DIM  128
#define OUTD 16
#define PITCH 68

typedef unsigned long long u64;

__device__ __forceinline__ float tanh_fast(float x) {
    float y; asm("tanh.approx.f32 %0, %1;" : "=f"(y) : "f"(x)); return y;
}
__device__ __forceinline__ u64 pack2(float lo, float hi) {
    u64 r; asm("mov.b64 %0, {%1, %2};" : "=l"(r) : "f"(lo), "f"(hi)); return r;
}
__device__ __forceinline__ void unpack2(u64 v, float& lo, float& hi) {
    asm("mov.b64 {%0, %1}, %2;" : "=f"(lo), "=f"(hi) : "l"(v));
}
__device__ __forceinline__ void ffma2(u64& d, u64 a, u64 b) {
    asm("fma.rn.f32x2 %0, %1, %2, %0;" : "+l"(d) : "l"(a), "l"(b));
}

__global__ __launch_bounds__(128)
void commnet_kernel(const float* __restrict__ obs,
                    const float* __restrict__ wH1,
                    const float* __restrict__ wH2,
                    const float* __restrict__ wC2,
                    const float* __restrict__ wout,
                    const float* __restrict__ bout,
                    float* __restrict__ out)
{
    // sh: h2 tile [128][68] floats (34,816 B); after GEMV reused as
    //     partials part[4 dg][64 n][16 o] floats (16,384 B).
    __shared__ __align__(16) float sh[DIM * PITCH];
    __shared__ __align__(16) float wsm[DIM * OUTD];   // 8 KB
    __shared__ float bsm[OUTD];

    const int tid = threadIdx.x;                      // = feature d for phase
    const int b   = blockIdx.x;

    // ---- stage w_out / b_out ----
    {
        const float4* w4  = (const float4*)wout;
        float4*       ws4 = (float4*)wsm;
        #pragma unroll
        for (int i = 0; i < 4; i++)
            ws4[i * 128 + tid] = w4[i * 128 + tid];
        if (tid < OUTD) bsm[tid] = bout[tid];
    }

    const float a1 = wH1[tid];
    const float a2 = wH2[tid];
    const float c2 = wC2[tid];
    const float* ob = obs + (size_t)b * (N_AG * DIM) + tid;

    // ---- pass 1: sum_n tanh(a1 * obs[n][d])  (coalesced LDG, no x[] regs) ----
    float sum = 0.0f;
    #pragma unroll 16
    for (int n = 0; n < N_AG; n++)
        sum += tanh_fast(a1 * ob[n * DIM]);
    const float inv = 1.0f / (float)(N_AG - 1);

    // ---- pass 2: reload obs (L1-hit), h2 -> tile row d, STS.128 per quad ----
    {
        float* row = &sh[tid * PITCH];
        #pragma unroll 4
        for (int m = 0; m < 16; m++) {
            float h2v[4];
            #pragma unroll
            for (int e = 0; e < 4; e++) {
                float xv = ob[(4 * m + e) * DIM];
                float h1 = tanh_fast(a1 * xv);
                h2v[e] = tanh_fast(a2 * h1 + c2 * (sum - h1) * inv) + xv;
            }
            *(float4*)&row[4 * m] = make_float4(h2v[0], h2v[1], h2v[2], h2v[3]);
        }
    }
    __syncthreads();

    // ---- GEMV: warp wd = d-quarter; lane = (p agent-octet, q o-quad) ----
    const int wd = tid >> 5;
    const int p  = (tid >> 2) & 7;
    const int q  = tid & 3;

    u64 acc[4][4];                         // [agent-pair ap][o]; pairs natural
    #pragma unroll
    for (int ap = 0; ap < 4; ap++)
        #pragma unroll
        for (int o = 0; o < 4; o++) acc[ap][o] = 0ull;

    #pragma unroll 8
    for (int i = 0; i < 32; i++) {
        const int d = 32 * wd + i;
        const ulonglong2* hp = (const ulonglong2*)&sh[d * PITCH + 8 * p];
        ulonglong2 h01 = hp[0];            // agents (8p,8p+1),(8p+2,8p+3)
        ulonglong2 h23 = hp[1];            // agents (8p+4,8p+5),(8p+6,8p+7)
        float4 wq = *(const float4*)&wsm[d * OUTD + 4 * q];
        u64 w0 = pack2(wq.x, wq.x);
        u64 w1 = pack2(wq.y, wq.y);
        u64 w2 = pack2(wq.z, wq.z);
        u64 w3 = pack2(wq.w, wq.w);

        ffma2(acc[0][0], h01.x, w0); ffma2(acc[0][1], h01.x, w1);
        ffma2(acc[0][2], h01.x, w2); ffma2(acc[0][3], h01.x, w3);
        ffma2(acc[1][0], h01.y, w0); ffma2(acc[1][1], h01.y, w1);
        ffma2(acc[1][2], h01.y, w2); ffma2(acc[1][3], h01.y, w3);
        ffma2(acc[2][0], h23.x, w0); ffma2(acc[2][1], h23.x, w1);
        ffma2(acc[2][2], h23.x, w2); ffma2(acc[2][3], h23.x, w3);
        ffma2(acc[3][0], h23.y, w0); ffma2(acc[3][1], h23.y, w1);
        ffma2(acc[3][2], h23.y, w2); ffma2(acc[3][3], h23.y, w3);
    }
    __syncthreads();                       // all tile reads complete

    // ---- partials: part[wd][n][16], quad-column swizzle c = q ^ (p&3) ----
    {
        float* part = sh;
        const int c4 = 4 * (q ^ (p & 3));
        #pragma unroll
        for (int ap = 0; ap < 4; ap++) {
            float l0, h0, l1, h1, l2, h2, l3, h3;
            unpack2(acc[ap][0], l0, h0);
            unpack2(acc[ap][1], l1, h1);
            unpack2(acc[ap][2], l2, h2);
            unpack2(acc[ap][3], l3, h3);
            const int n0 = 8 * p + 2 * ap;
            *(float4*)&part[wd * 1024 + n0 * 16 + c4]       = make_float4(l0, l1, l2, l3);
            *(float4*)&part[wd * 1024 + (n0 + 1) * 16 + c4] = make_float4(h0, h1, h2, h3);
        }
    }
    __syncthreads();

    // ---- combine + store: thread t -> agent n = t>>1, o-half (t&1)*8 ----
    {
        const float* part = sh;
        const int n   = tid >> 1;
        const int jh  = tid & 1;
        const int pn3 = (n >> 3) & 3;

        #pragma unroll
        for (int jj = 0; jj < 2; jj++) {
            const int j  = 2 * jh + jj;            // output quad index
            const int c4 = 4 * (j ^ pn3);          // physical column
            float4 s0 = *(const float4*)&part[0 * 1024 + n * 16 + c4];
            float4 s1 = *(const float4*)&part[1 * 1024 + n * 16 + c4];
            float4 s2 = *(const float4*)&part[2 * 1024 + n * 16 + c4];
            float4 s3 = *(const float4*)&part[3 * 1024 + n * 16 + c4];
            float4 bq = *(const float4*)&bsm[4 * j];
            float4 r;
            r.x = s0.x + s1.x + s2.x + s3.x + bq.x;
            r.y = s0.y + s1.y + s2.y + s3.y + bq.y;
            r.z = s0.z + s1.z + s2.z + s3.z + bq.z;
            r.w = s0.w + s1.w + s2.w + s3.w + bq.w;
            *(float4*)&out[(size_t)b * (N_AG * OUTD) + n * OUTD + 4 * j] = r;
        }
    }
}

extern "C" void kernel_launch(void* const* d_in, const int* in_sizes, int n_in,
                              void* d_out, int out_size) {
    const float* obs  = (const float*)d_in[0];
    const float* wH1  = (const float*)d_in[1];
    // d_in[2] = w_C1: multiplies C0 = 0 -> unused
    const float* wH2  = (const float*)d_in[3];
    const float* wC2  = (const float*)d_in[4];
    const float* wout = (const float*)d_in[5];
    const float* bout = (const float*)d_in[6];
    float* out = (float*)d_out;

    int B = in_sizes[0] / (N_AG * DIM);   // 8192
    commnet_kernel<<<B, 128>>>(obs, wH1, wH2, wC2, wout, bout, out);
}

// round 10
// speedup vs baseline: 2.1180x; 1.2203x over previous
#include <cuda_runtime.h>

// CommNet forward: B=8192, N=64, D=128, O=16
//   H1 = tanh(wH1*obs); C1 = (sum_n H1 - H1)/(N-1)
//   H2 = tanh(wH2*H1 + wC2*C1) + obs ; out = H2 @ w_out + b_out
//
// One CTA per batch element, 128 threads.
// Phase (R6-proven): thread = feature d; obs column read ONCE into x[64]
//   registers; sum + h2 computed register-resident; h2 -> tile STS.128.
// GEMV (R9-proven): warp = d-quarter; lane = (agent-octet p, o-quad q);
//   per d: 2 h-LDS.128 (natural u64 agent pairs) + 1 w-LDS.128 -> 16 FFMA2.
// 4-way d-reduction via quad-swizzled smem partials overlaid on the tile.

#define N_AG 64
#define DIM  128
#define OUTD 16
#define PITCH 68   // floats; 17 16B-units (odd) -> conflict-free row-strided 128b ops

typedef unsigned long long u64;

__device__ __forceinline__ float tanh_fast(float x) {
    float y; asm("tanh.approx.f32 %0, %1;" : "=f"(y) : "f"(x)); return y;
}
__device__ __forceinline__ u64 pack2(float lo, float hi) {
    u64 r; asm("mov.b64 %0, {%1, %2};" : "=l"(r) : "f"(lo), "f"(hi)); return r;
}
__device__ __forceinline__ void unpack2(u64 v, float& lo, float& hi) {
    asm("mov.b64 {%0, %1}, %2;" : "=f"(lo), "=f"(hi) : "l"(v));
}
__device__ __forceinline__ void ffma2(u64& d, u64 a, u64 b) {
    asm("fma.rn.f32x2 %0, %1, %2, %0;" : "+l"(d) : "l"(a), "l"(b));
}

__global__ __launch_bounds__(128)
void commnet_kernel(const float* __restrict__ obs,
                    const float* __restrict__ wH1,
                    const float* __restrict__ wH2,
                    const float* __restrict__ wC2,
                    const float* __restrict__ wout,
                    const float* __restrict__ bout,
                    float* __restrict__ out)
{
    // sh: h2 tile [128][68] floats (34,816 B); after GEMV reused as
    //     partials part[4 dg][64 n][16 o] floats (16,384 B).
    __shared__ __align__(16) float sh[DIM * PITCH];
    __shared__ __align__(16) float wsm[DIM * OUTD];   // 8 KB
    __shared__ float bsm[OUTD];

    const int tid = threadIdx.x;                      // = feature d for phase
    const int b   = blockIdx.x;

    // ---- stage w_out / b_out ----
    {
        const float4* w4  = (const float4*)wout;
        float4*       ws4 = (float4*)wsm;
        #pragma unroll
        for (int i = 0; i < 4; i++)
            ws4[i * 128 + tid] = w4[i * 128 + tid];
        if (tid < OUTD) bsm[tid] = bout[tid];
    }

    // ---- obs column d=tid into registers: 64 coalesced LDG.32 (read ONCE) ----
    const float* ob = obs + (size_t)b * (N_AG * DIM) + tid;
    float x[N_AG];
    #pragma unroll
    for (int n = 0; n < N_AG; n++)
        x[n] = ob[n * DIM];

    const float a1 = wH1[tid];
    const float a2 = wH2[tid];
    const float c2 = wC2[tid];

    // ---- pass 1: sum of tanh over agents (registers only) ----
    float sum = 0.0f;
    #pragma unroll
    for (int n = 0; n < N_AG; n++)
        sum += tanh_fast(a1 * x[n]);
    const float inv = 1.0f / (float)(N_AG - 1);

    // ---- pass 2: h2 per chunk of 4 agents -> tile row d, STS.128 ----
    {
        float* row = &sh[tid * PITCH];
        #pragma unroll
        for (int m = 0; m < 16; m++) {
            float h2v[4];
            #pragma unroll
            for (int e = 0; e < 4; e++) {
                float xv = x[4 * m + e];
                float h1 = tanh_fast(a1 * xv);
                h2v[e] = tanh_fast(a2 * h1 + c2 * (sum - h1) * inv) + xv;
            }
            *(float4*)&row[4 * m] = make_float4(h2v[0], h2v[1], h2v[2], h2v[3]);
        }
    }
    __syncthreads();

    // ---- GEMV: warp wd = d-quarter; lane = (p agent-octet, q o-quad) ----
    const int wd = tid >> 5;
    const int p  = (tid >> 2) & 7;
    const int q  = tid & 3;

    u64 acc[4][4];                         // [agent-pair ap][o]; pairs natural
    #pragma unroll
    for (int ap = 0; ap < 4; ap++)
        #pragma unroll
        for (int o = 0; o < 4; o++) acc[ap][o] = 0ull;

    #pragma unroll 8
    for (int i = 0; i < 32; i++) {
        const int d = 32 * wd + i;
        const ulonglong2* hp = (const ulonglong2*)&sh[d * PITCH + 8 * p];
        ulonglong2 h01 = hp[0];            // agents (8p,8p+1),(8p+2,8p+3)
        ulonglong2 h23 = hp[1];            // agents (8p+4,8p+5),(8p+6,8p+7)
        float4 wq = *(const float4*)&wsm[d * OUTD + 4 * q];
        u64 w0 = pack2(wq.x, wq.x);
        u64 w1 = pack2(wq.y, wq.y);
        u64 w2 = pack2(wq.z, wq.z);
        u64 w3 = pack2(wq.w, wq.w);

        ffma2(acc[0][0], h01.x, w0); ffma2(acc[0][1], h01.x, w1);
        ffma2(acc[0][2], h01.x, w2); ffma2(acc[0][3], h01.x, w3);
        ffma2(acc[1][0], h01.y, w0); ffma2(acc[1][1], h01.y, w1);
        ffma2(acc[1][2], h01.y, w2); ffma2(acc[1][3], h01.y, w3);
        ffma2(acc[2][0], h23.x, w0); ffma2(acc[2][1], h23.x, w1);
        ffma2(acc[2][2], h23.x, w2); ffma2(acc[2][3], h23.x, w3);
        ffma2(acc[3][0], h23.y, w0); ffma2(acc[3][1], h23.y, w1);
        ffma2(acc[3][2], h23.y, w2); ffma2(acc[3][3], h23.y, w3);
    }
    __syncthreads();                       // all tile reads complete

    // ---- partials: part[wd][n][16], quad-column swizzle c = q ^ (p&3) ----
    {
        float* part = sh;
        const int c4 = 4 * (q ^ (p & 3));
        #pragma unroll
        for (int ap = 0; ap < 4; ap++) {
            float l0, h0, l1, h1, l2, h2, l3, h3;
            unpack2(acc[ap][0], l0, h0);
            unpack2(acc[ap][1], l1, h1);
            unpack2(acc[ap][2], l2, h2);
            unpack2(acc[ap][3], l3, h3);
            const int n0 = 8 * p + 2 * ap;
            *(float4*)&part[wd * 1024 + n0 * 16 + c4]       = make_float4(l0, l1, l2, l3);
            *(float4*)&part[wd * 1024 + (n0 + 1) * 16 + c4] = make_float4(h0, h1, h2, h3);
        }
    }
    __syncthreads();

    // ---- combine + store: thread t -> agent n = t>>1, o-half (t&1)*8 ----
    {
        const float* part = sh;
        const int n   = tid >> 1;
        const int jh  = tid & 1;
        const int pn3 = (n >> 3) & 3;

        #pragma unroll
        for (int jj = 0; jj < 2; jj++) {
            const int j  = 2 * jh + jj;            // output quad index
            const int c4 = 4 * (j ^ pn3);          // physical column
            float4 s0 = *(const float4*)&part[0 * 1024 + n * 16 + c4];
            float4 s1 = *(const float4*)&part[1 * 1024 + n * 16 + c4];
            float4 s2 = *(const float4*)&part[2 * 1024 + n * 16 + c4];
            float4 s3 = *(const float4*)&part[3 * 1024 + n * 16 + c4];
            float4 bq = *(const float4*)&bsm[4 * j];
            float4 r;
            r.x = s0.x + s1.x + s2.x + s3.x + bq.x;
            r.y = s0.y + s1.y + s2.y + s3.y + bq.y;
            r.z = s0.z + s1.z + s2.z + s3.z + bq.z;
            r.w = s0.w + s1.w + s2.w + s3.w + bq.w;
            *(float4*)&out[(size_t)b * (N_AG * OUTD) + n * OUTD + 4 * j] = r;
        }
    }
}

extern "C" void kernel_launch(void* const* d_in, const int* in_sizes, int n_in,
                              void* d_out, int out_size) {
    const float* obs  = (const float*)d_in[0];
    const float* wH1  = (const float*)d_in[1];
    // d_in[2] = w_C1: multiplies C0 = 0 -> unused
    const float* wH2  = (const float*)d_in[3];
    const float* wC2  = (const float*)d_in[4];
    const float* wout = (const float*)d_in[5];
    const float* bout = (const float*)d_in[6];
    float* out = (float*)d_out;

    int B = in_sizes[0] / (N_AG * DIM);   // 8192
    commnet_kernel<<<B, 128>>>(obs, wH1, wH2, wC2, wout, bout, out);
}